// round 1
// baseline (speedup 1.0000x reference)
#include <cuda_runtime.h>
#include <math.h>

// ---------------------------------------------------------------------------
// LocalWindowAttention: out = Attn(x@Wq^T, x@Wk^T, x@Wv^T; window=16) @ Wo^T
// Shapes: x [2,4096,1024], W* [1024,1024] (row-major, applied transposed),
//         16 heads x 64 dims, window 16 (left pad 8, right pad 7).
// R0 baseline: fp32 SIMT GEMMs (128x128x8 register-blocked) + warp-per-token
// windowed attention. All intermediates in __device__ globals (no allocs).
// ---------------------------------------------------------------------------

#define BATCH   2
#define S_LEN   4096
#define DMODEL  1024
#define NHEAD   16
#define HDIM    64
#define WIN     16
#define LPAD    8

#define M_ROWS  (BATCH * S_LEN)          // 8192
#define ELEMS   (M_ROWS * DMODEL)        // 8,388,608

static __device__ float g_q[ELEMS];
static __device__ float g_k[ELEMS];
static __device__ float g_v[ELEMS];
static __device__ float g_att[ELEMS];

// ---------------------------------------------------------------------------
// GEMM: C[m][n] = sum_k A[m][k] * B[n][k]   (NT: both K-contiguous)
// BM=BN=128, BK=8, 256 threads, 8x8 per-thread microtile, register-staged
// global->shared prefetch. M,N,K are compile-time-fixed multiples of tiles.
// ---------------------------------------------------------------------------
#define BM 128
#define BN 128
#define BK 8
#define SMPAD 132   // 128 + 4 pad: conflict-free STS, keeps 16B row alignment

__device__ __forceinline__ void gemm_body(const float* __restrict__ A,
                                          const float* __restrict__ B,
                                          float* __restrict__ C)
{
    const int M = M_ROWS, N = DMODEL, K = DMODEL;

    __shared__ __align__(16) float As[BK][SMPAD];
    __shared__ __align__(16) float Bs[BK][SMPAD];

    const int t  = threadIdx.x;
    const int tx = t & 15;       // -> N microtile
    const int ty = t >> 4;       // -> M microtile
    const int m0 = blockIdx.y * BM;
    const int n0 = blockIdx.x * BN;

    // gmem load mapping: 2 threads per row, one float4 each
    const int lrow = t >> 1;           // 0..127
    const int lcol = (t & 1) * 4;      // 0 or 4

    const float* pA = A + (size_t)(m0 + lrow) * K + lcol;
    const float* pB = B + (size_t)(n0 + lrow) * K + lcol;

    float acc[8][8];
#pragma unroll
    for (int i = 0; i < 8; ++i)
#pragma unroll
        for (int j = 0; j < 8; ++j) acc[i][j] = 0.0f;

    float4 ra = *(const float4*)pA;
    float4 rb = *(const float4*)pB;

    const int nk = K / BK;   // 128
    for (int kt = 0; kt < nk; ++kt) {
        As[lcol + 0][lrow] = ra.x;
        As[lcol + 1][lrow] = ra.y;
        As[lcol + 2][lrow] = ra.z;
        As[lcol + 3][lrow] = ra.w;
        Bs[lcol + 0][lrow] = rb.x;
        Bs[lcol + 1][lrow] = rb.y;
        Bs[lcol + 2][lrow] = rb.z;
        Bs[lcol + 3][lrow] = rb.w;
        __syncthreads();

        if (kt + 1 < nk) {           // prefetch next tile; overlaps compute
            pA += BK; pB += BK;
            ra = *(const float4*)pA;
            rb = *(const float4*)pB;
        }

#pragma unroll
        for (int k = 0; k < BK; ++k) {
            float4 a0 = *(const float4*)&As[k][ty * 4];
            float4 a1 = *(const float4*)&As[k][64 + ty * 4];
            float4 b0 = *(const float4*)&Bs[k][tx * 4];
            float4 b1 = *(const float4*)&Bs[k][64 + tx * 4];
            float a[8] = {a0.x, a0.y, a0.z, a0.w, a1.x, a1.y, a1.z, a1.w};
            float b[8] = {b0.x, b0.y, b0.z, b0.w, b1.x, b1.y, b1.z, b1.w};
#pragma unroll
            for (int i = 0; i < 8; ++i)
#pragma unroll
                for (int j = 0; j < 8; ++j)
                    acc[i][j] = fmaf(a[i], b[j], acc[i][j]);
        }
        __syncthreads();
    }

#pragma unroll
    for (int i = 0; i < 8; ++i) {
        int row = m0 + ((i < 4) ? (ty * 4 + i) : (64 + ty * 4 + (i - 4)));
        float* pc = C + (size_t)row * N + n0;
        *(float4*)&pc[tx * 4]      = make_float4(acc[i][0], acc[i][1], acc[i][2], acc[i][3]);
        *(float4*)&pc[64 + tx * 4] = make_float4(acc[i][4], acc[i][5], acc[i][6], acc[i][7]);
    }
}

// grid (N/BN, M/BM, 3): z selects Q/K/V — one launch for all three projections
__global__ __launch_bounds__(256, 2)
void k_qkv(const float* __restrict__ x,
           const float* __restrict__ Wq,
           const float* __restrict__ Wk,
           const float* __restrict__ Wv)
{
    const float* Bm = (blockIdx.z == 0) ? Wq : (blockIdx.z == 1) ? Wk : Wv;
    float*       Cm = (blockIdx.z == 0) ? g_q : (blockIdx.z == 1) ? g_k : g_v;
    gemm_body(x, Bm, Cm);
}

__global__ __launch_bounds__(256, 2)
void k_proj_out(const float* __restrict__ Wo, float* __restrict__ out)
{
    gemm_body(g_att, Wo, out);
}

// ---------------------------------------------------------------------------
// Windowed attention: one warp per (b, h, s). Each lane owns 2 of the 64 head
// dims (float2). 16 scores via shuffle-reduced dots, register softmax,
// weighted V accumulation. Consecutive warps = consecutive s -> K/V rows hit
// in L1/L2 (each row reused by ~16 neighboring tokens).
// ---------------------------------------------------------------------------
__global__ __launch_bounds__(256)
void k_attn(float* __restrict__ dummy)  // buffers are device globals
{
    (void)dummy;
    const int wg   = (int)((blockIdx.x * blockDim.x + threadIdx.x) >> 5);
    const int lane = threadIdx.x & 31;

    const int s = wg & (S_LEN - 1);
    const int h = (wg >> 12) & (NHEAD - 1);
    const int b = wg >> 16;

    const size_t rowbase = ((size_t)(b * S_LEN + s)) * DMODEL + h * HDIM;
    const float2 qv = *(const float2*)(g_q + rowbase + 2 * lane);

    float sc[WIN];
#pragma unroll
    for (int j = 0; j < WIN; ++j) {
        const int sp = s + j - LPAD;
        float val = -1e30f;
        if (sp >= 0 && sp < S_LEN) {
            const size_t kb = ((size_t)(b * S_LEN + sp)) * DMODEL + h * HDIM;
            const float2 kv = *(const float2*)(g_k + kb + 2 * lane);
            float p = qv.x * kv.x + qv.y * kv.y;
            p += __shfl_xor_sync(0xffffffffu, p, 16);
            p += __shfl_xor_sync(0xffffffffu, p, 8);
            p += __shfl_xor_sync(0xffffffffu, p, 4);
            p += __shfl_xor_sync(0xffffffffu, p, 2);
            p += __shfl_xor_sync(0xffffffffu, p, 1);
            val = p * 0.125f;   // 1/sqrt(64)
        }
        sc[j] = val;
    }

    float mx = sc[0];
#pragma unroll
    for (int j = 1; j < WIN; ++j) mx = fmaxf(mx, sc[j]);

    float den = 0.0f, ax = 0.0f, ay = 0.0f;
#pragma unroll
    for (int j = 0; j < WIN; ++j) {
        const int sp = s + j - LPAD;
        if (sp >= 0 && sp < S_LEN) {
            const float p = __expf(sc[j] - mx);
            den += p;
            const size_t vb = ((size_t)(b * S_LEN + sp)) * DMODEL + h * HDIM;
            const float2 vv = *(const float2*)(g_v + vb + 2 * lane);
            ax = fmaf(p, vv.x, ax);
            ay = fmaf(p, vv.y, ay);
        }
    }
    const float inv = 1.0f / den;
    *(float2*)(g_att + rowbase + 2 * lane) = make_float2(ax * inv, ay * inv);
}

// ---------------------------------------------------------------------------
extern "C" void kernel_launch(void* const* d_in, const int* in_sizes, int n_in,
                              void* d_out, int out_size)
{
    (void)in_sizes; (void)n_in; (void)out_size;
    const float* x  = (const float*)d_in[0];
    const float* Wq = (const float*)d_in[1];
    const float* Wk = (const float*)d_in[2];
    const float* Wv = (const float*)d_in[3];
    const float* Wo = (const float*)d_in[4];
    float* out = (float*)d_out;

    dim3 gblk(256);
    dim3 ggrid(DMODEL / BN, M_ROWS / BM, 3);   // (8, 64, 3)
    k_qkv<<<ggrid, gblk>>>(x, Wq, Wk, Wv);

    const int total_warps = BATCH * NHEAD * S_LEN;          // 131072
    const int blocks = total_warps / 8;                     // 256 thr = 8 warps
    k_attn<<<blocks, 256>>>(nullptr);

    dim3 ogrid(DMODEL / BN, M_ROWS / BM, 1);
    k_proj_out<<<ogrid, 256>>>(Wo, out);
}

// round 6
// speedup vs baseline: 1.6214x; 1.6214x over previous
#include <cuda_runtime.h>
#include <cuda_bf16.h>
#include <cstdint>
#include <math.h>

// ---------------------------------------------------------------------------
// LocalWindowAttention via split-bf16 mma.sync GEMMs (plain-sm_100 ISA; the
// harness compiles for sm_100 where tcgen05 is unavailable).
//   C = Ah*Bh + Ah*Bl + Al*Bh  expressed as one GEMM over virtual K' = 3072.
// Tile: BM=BN=128, BK=32, 256 thr, warp tile 64x32, double-buffered cp.async.
// R6 == R5 (re-run: R5 failed on container acquisition, not kernel content).
// ---------------------------------------------------------------------------

#define BATCH   2
#define S_LEN   4096
#define DMODEL  1024
#define NHEAD   16
#define HDIM    64
#define WIN     16
#define LPAD    8

#define M_ROWS  (BATCH * S_LEN)          // 8192
#define ELEMS   (M_ROWS * DMODEL)        // 8,388,608
#define WELEMS  (DMODEL * DMODEL)        // 1,048,576

static __device__ float g_q[ELEMS];
static __device__ float g_k[ELEMS];
static __device__ float g_v[ELEMS];
static __device__ __align__(256) __nv_bfloat16 g_xh[ELEMS];
static __device__ __align__(256) __nv_bfloat16 g_xl[ELEMS];
static __device__ __align__(256) __nv_bfloat16 g_ah[ELEMS];
static __device__ __align__(256) __nv_bfloat16 g_al[ELEMS];
static __device__ __align__(256) __nv_bfloat16 g_wh[4][WELEMS];
static __device__ __align__(256) __nv_bfloat16 g_wl[4][WELEMS];

// ---------------------------------------------------------------------------
__device__ __forceinline__ uint32_t smem_u32(const void* p) {
    uint32_t a;
    asm("{ .reg .u64 t; cvta.to.shared.u64 t, %1; cvt.u32.u64 %0, t; }"
        : "=r"(a) : "l"(p));
    return a;
}
__device__ __forceinline__ void cp16(uint32_t sdst, const void* gsrc) {
    asm volatile("cp.async.cg.shared.global [%0], [%1], 16;" :: "r"(sdst), "l"(gsrc));
}
#define CP_COMMIT() asm volatile("cp.async.commit_group;" ::: "memory")
#define CP_WAIT(n)  asm volatile("cp.async.wait_group %0;" :: "n"(n) : "memory")

__device__ __forceinline__ void ldsm_x4(uint32_t* r, uint32_t addr) {
    asm volatile("ldmatrix.sync.aligned.m8n8.x4.shared.b16 {%0,%1,%2,%3}, [%4];"
                 : "=r"(r[0]), "=r"(r[1]), "=r"(r[2]), "=r"(r[3]) : "r"(addr));
}
__device__ __forceinline__ void ldsm_x2(uint32_t* r, uint32_t addr) {
    asm volatile("ldmatrix.sync.aligned.m8n8.x2.shared.b16 {%0,%1}, [%2];"
                 : "=r"(r[0]), "=r"(r[1]) : "r"(addr));
}
__device__ __forceinline__ void mma_bf16(float* c, const uint32_t* a, const uint32_t* b) {
    asm volatile(
        "mma.sync.aligned.m16n8k16.row.col.f32.bf16.bf16.f32 "
        "{%0,%1,%2,%3}, {%4,%5,%6,%7}, {%8,%9}, {%0,%1,%2,%3};"
        : "+f"(c[0]), "+f"(c[1]), "+f"(c[2]), "+f"(c[3])
        : "r"(a[0]), "r"(a[1]), "r"(a[2]), "r"(a[3]), "r"(b[0]), "r"(b[1]));
}

// ---------------------------------------------------------------------------
// GEMM geometry
// ---------------------------------------------------------------------------
#define PITCH   80            // smem row pitch (bytes): conflict-free ldmatrix
#define TILE_B  (128 * PITCH) // 10240 bytes per operand tile
#define NKT     96            // virtual K' = 3072, BK = 32
#define TPB     256

__device__ __forceinline__ void load_tile(uint32_t sA, uint32_t sB, int t,
                                          int m0, int n0,
                                          const __nv_bfloat16* Ah,
                                          const __nv_bfloat16* Al,
                                          const __nv_bfloat16* Bh,
                                          const __nv_bfloat16* Bl, int tid)
{
    const int pass = t >> 5;                 // 0: Ah*Bh, 1: Ah*Bl, 2: Al*Bh
    const int kb2  = (t & 31) * 64;          // byte offset within a 2048B row
    const char* As = (const char*)((pass == 2) ? Al : Ah) + (size_t)m0 * 2048 + kb2;
    const char* Bs = (const char*)((pass == 1) ? Bl : Bh) + (size_t)n0 * 2048 + kb2;
    const uint32_t dA = sA + (t & 1) * TILE_B;
    const uint32_t dB = sB + (t & 1) * TILE_B;
#pragma unroll
    for (int i = 0; i < 2; ++i) {            // 512 chunks per operand / 256 thr
        const int g = tid + i * TPB;
        const int row = g >> 2, c = g & 3;   // 4 x 16B chunks per 64B row seg
        cp16(dA + row * PITCH + c * 16, As + (size_t)row * 2048 + c * 16);
        cp16(dB + row * PITCH + c * 16, Bs + (size_t)row * 2048 + c * 16);
    }
}

__device__ __forceinline__ void gemm_body(const __nv_bfloat16* Ah,
                                          const __nv_bfloat16* Al,
                                          const __nv_bfloat16* Bh,
                                          const __nv_bfloat16* Bl,
                                          float* __restrict__ C)
{
    __shared__ __align__(16) unsigned char smA[2 * TILE_B];
    __shared__ __align__(16) unsigned char smB[2 * TILE_B];

    const int tid  = threadIdx.x;
    const int lane = tid & 31, wid = tid >> 5;
    const int wm = wid & 1;                  // 2 warps along M: 64 rows each
    const int wn = wid >> 1;                 // 4 warps along N: 32 cols each
    const int m0 = blockIdx.y * 128, n0 = blockIdx.x * 128;

    const uint32_t sA = smem_u32(smA);
    const uint32_t sB = smem_u32(smB);

    // per-thread ldmatrix base addresses (buffer 0)
    const uint32_t aBase0 = sA + (wm * 64 + (lane & 15)) * PITCH + ((lane >> 4) * 16);
    const uint32_t bBase0 = sB + (wn * 32 + (lane & 7)) * PITCH + (((lane >> 3) & 1) * 16);

    float acc[4][4][4];
#pragma unroll
    for (int i = 0; i < 4; ++i)
#pragma unroll
        for (int j = 0; j < 4; ++j)
#pragma unroll
            for (int r = 0; r < 4; ++r) acc[i][j][r] = 0.0f;

    load_tile(sA, sB, 0, m0, n0, Ah, Al, Bh, Bl, tid);
    CP_COMMIT();

    for (int kt = 0; kt < NKT; ++kt) {
        if (kt < NKT - 1) {
            load_tile(sA, sB, kt + 1, m0, n0, Ah, Al, Bh, Bl, tid);
            CP_COMMIT();
            CP_WAIT(1);          // tile kt's group complete; kt+1 in flight
        } else {
            CP_WAIT(0);
        }
        __syncthreads();         // tile kt visible to all warps

        const uint32_t aB = aBase0 + (kt & 1) * TILE_B;
        const uint32_t bB = bBase0 + (kt & 1) * TILE_B;
#pragma unroll
        for (int ks = 0; ks < 2; ++ks) {     // two k16 steps per BK=32
            uint32_t a[4][4], b[4][2];
#pragma unroll
            for (int mi = 0; mi < 4; ++mi)
                ldsm_x4(a[mi], aB + mi * (16 * PITCH) + ks * 32);
#pragma unroll
            for (int ni = 0; ni < 4; ++ni)
                ldsm_x2(b[ni], bB + ni * (8 * PITCH) + ks * 32);
#pragma unroll
            for (int mi = 0; mi < 4; ++mi)
#pragma unroll
                for (int ni = 0; ni < 4; ++ni)
                    mma_bf16(acc[mi][ni], a[mi], b[ni]);
        }
        __syncthreads();         // all reads of this buffer done before refill
    }

    // epilogue: direct fp32 stores (float2 per half-tile row)
#pragma unroll
    for (int mi = 0; mi < 4; ++mi) {
#pragma unroll
        for (int ni = 0; ni < 4; ++ni) {
            const int m = m0 + wm * 64 + mi * 16 + (lane >> 2);
            const int n = n0 + wn * 32 + ni * 8 + 2 * (lane & 3);
            *(float2*)&C[(size_t)m * DMODEL + n] =
                make_float2(acc[mi][ni][0], acc[mi][ni][1]);
            *(float2*)&C[(size_t)(m + 8) * DMODEL + n] =
                make_float2(acc[mi][ni][2], acc[mi][ni][3]);
        }
    }
}

__global__ __launch_bounds__(TPB, 2)
void k_qkv_mma()
{
    const int z = blockIdx.z;
    float* C = (z == 0) ? g_q : (z == 1) ? g_k : g_v;
    gemm_body(g_xh, g_xl, g_wh[z], g_wl[z], C);
}

__global__ __launch_bounds__(TPB, 2)
void k_out_mma(float* __restrict__ out)
{
    gemm_body(g_ah, g_al, g_wh[3], g_wl[3], out);
}

// ---------------------------------------------------------------------------
// fp32 -> (hi, lo) bf16 split
// ---------------------------------------------------------------------------
__global__ __launch_bounds__(256)
void k_split(const float* __restrict__ src, __nv_bfloat16* __restrict__ dh,
             __nv_bfloat16* __restrict__ dl, int n)
{
    const int i = (blockIdx.x * 256 + threadIdx.x) * 4;
    if (i >= n) return;
    const float4 v = *(const float4*)(src + i);
    __nv_bfloat16 h0 = __float2bfloat16(v.x);
    __nv_bfloat16 h1 = __float2bfloat16(v.y);
    __nv_bfloat16 h2 = __float2bfloat16(v.z);
    __nv_bfloat16 h3 = __float2bfloat16(v.w);
    __nv_bfloat16 l0 = __float2bfloat16(v.x - __bfloat162float(h0));
    __nv_bfloat16 l1 = __float2bfloat16(v.y - __bfloat162float(h1));
    __nv_bfloat16 l2 = __float2bfloat16(v.z - __bfloat162float(h2));
    __nv_bfloat16 l3 = __float2bfloat16(v.w - __bfloat162float(h3));
    *(__nv_bfloat162*)(dh + i)     = __nv_bfloat162(h0, h1);
    *(__nv_bfloat162*)(dh + i + 2) = __nv_bfloat162(h2, h3);
    *(__nv_bfloat162*)(dl + i)     = __nv_bfloat162(l0, l1);
    *(__nv_bfloat162*)(dl + i + 2) = __nv_bfloat162(l2, l3);
}

// ---------------------------------------------------------------------------
// Windowed attention: one warp per (b, h, s); emits bf16 hi/lo split.
// ---------------------------------------------------------------------------
__global__ __launch_bounds__(256)
void k_attn()
{
    const int wg   = (int)((blockIdx.x * blockDim.x + threadIdx.x) >> 5);
    const int lane = threadIdx.x & 31;

    const int s = wg & (S_LEN - 1);
    const int h = (wg >> 12) & (NHEAD - 1);
    const int b = wg >> 16;

    const size_t rowbase = ((size_t)(b * S_LEN + s)) * DMODEL + h * HDIM;
    const float2 qv = *(const float2*)(g_q + rowbase + 2 * lane);

    float sc[WIN];
#pragma unroll
    for (int j = 0; j < WIN; ++j) {
        const int sp = s + j - LPAD;
        float val = -1e30f;
        if (sp >= 0 && sp < S_LEN) {
            const size_t kb = ((size_t)(b * S_LEN + sp)) * DMODEL + h * HDIM;
            const float2 kv = *(const float2*)(g_k + kb + 2 * lane);
            float p = qv.x * kv.x + qv.y * kv.y;
            p += __shfl_xor_sync(0xffffffffu, p, 16);
            p += __shfl_xor_sync(0xffffffffu, p, 8);
            p += __shfl_xor_sync(0xffffffffu, p, 4);
            p += __shfl_xor_sync(0xffffffffu, p, 2);
            p += __shfl_xor_sync(0xffffffffu, p, 1);
            val = p * 0.125f;   // 1/sqrt(64)
        }
        sc[j] = val;
    }

    float mx = sc[0];
#pragma unroll
    for (int j = 1; j < WIN; ++j) mx = fmaxf(mx, sc[j]);

    float den = 0.0f, ax = 0.0f, ay = 0.0f;
#pragma unroll
    for (int j = 0; j < WIN; ++j) {
        const int sp = s + j - LPAD;
        if (sp >= 0 && sp < S_LEN) {
            const float p = __expf(sc[j] - mx);
            den += p;
            const size_t vb = ((size_t)(b * S_LEN + sp)) * DMODEL + h * HDIM;
            const float2 vv = *(const float2*)(g_v + vb + 2 * lane);
            ax = fmaf(p, vv.x, ax);
            ay = fmaf(p, vv.y, ay);
        }
    }
    const float inv = 1.0f / den;
    const float ox = ax * inv, oy = ay * inv;
    const __nv_bfloat16 hx = __float2bfloat16(ox);
    const __nv_bfloat16 hy = __float2bfloat16(oy);
    const __nv_bfloat16 lx = __float2bfloat16(ox - __bfloat162float(hx));
    const __nv_bfloat16 ly = __float2bfloat16(oy - __bfloat162float(hy));
    *(__nv_bfloat162*)(g_ah + rowbase + 2 * lane) = __nv_bfloat162(hx, hy);
    *(__nv_bfloat162*)(g_al + rowbase + 2 * lane) = __nv_bfloat162(lx, ly);
}

// ---------------------------------------------------------------------------
extern "C" void kernel_launch(void* const* d_in, const int* in_sizes, int n_in,
                              void* d_out, int out_size)
{
    (void)in_sizes; (void)n_in; (void)out_size;
    const float* x  = (const float*)d_in[0];
    const float* Wq = (const float*)d_in[1];
    const float* Wk = (const float*)d_in[2];
    const float* Wv = (const float*)d_in[3];
    const float* Wo = (const float*)d_in[4];
    float* out = (float*)d_out;

    __nv_bfloat16 *xh, *xl, *wh, *wl;
    cudaGetSymbolAddress((void**)&xh, g_xh);
    cudaGetSymbolAddress((void**)&xl, g_xl);
    cudaGetSymbolAddress((void**)&wh, g_wh);
    cudaGetSymbolAddress((void**)&wl, g_wl);

    k_split<<<ELEMS / 1024, 256>>>(x,  xh, xl, ELEMS);
    k_split<<<WELEMS / 1024, 256>>>(Wq, wh + 0 * (size_t)WELEMS, wl + 0 * (size_t)WELEMS, WELEMS);
    k_split<<<WELEMS / 1024, 256>>>(Wk, wh + 1 * (size_t)WELEMS, wl + 1 * (size_t)WELEMS, WELEMS);
    k_split<<<WELEMS / 1024, 256>>>(Wv, wh + 2 * (size_t)WELEMS, wl + 2 * (size_t)WELEMS, WELEMS);
    k_split<<<WELEMS / 1024, 256>>>(Wo, wh + 3 * (size_t)WELEMS, wl + 3 * (size_t)WELEMS, WELEMS);

    k_qkv_mma<<<dim3(8, 64, 3), TPB>>>();

    const int total_warps = BATCH * NHEAD * S_LEN;          // 131072
    k_attn<<<total_warps / 8, 256>>>();

    k_out_mma<<<dim3(8, 64), TPB>>>(out);
}

// round 9
// speedup vs baseline: 2.0663x; 1.2744x over previous
#include <cuda_runtime.h>
#include <cuda_bf16.h>
#include <cstdint>
#include <math.h>

// ---------------------------------------------------------------------------
// LocalWindowAttention via split-bf16 mma.sync GEMMs (plain-sm_100 ISA).
//   C = Ah*Bh + Ah*Bl + Al*Bh  expressed as one GEMM over virtual K' = 3072.
// R9: NO cudaFuncSetAttribute (the _HX_ENFORCE "device limits changed" killer
// identified from the R2/R3/R7/R8 failure pattern). 3-stage pipeline in
// 48KB STATIC smem via XOR-swizzled 64B-pitch tiles; refill issued before
// compute (~2 compute bodies of cp.async slack); ONE barrier per K-tile;
// B-side ldmatrix x4. Tile: BM=BN=128, BK=32, 256 thr, warp tile 64x32.
// ---------------------------------------------------------------------------

#define BATCH   2
#define S_LEN   4096
#define DMODEL  1024
#define NHEAD   16
#define HDIM    64
#define WIN     16
#define LPAD    8

#define M_ROWS  (BATCH * S_LEN)          // 8192
#define ELEMS   (M_ROWS * DMODEL)        // 8,388,608
#define WELEMS  (DMODEL * DMODEL)        // 1,048,576

static __device__ float g_q[ELEMS];
static __device__ float g_k[ELEMS];
static __device__ float g_v[ELEMS];
static __device__ __align__(256) __nv_bfloat16 g_xh[ELEMS];
static __device__ __align__(256) __nv_bfloat16 g_xl[ELEMS];
static __device__ __align__(256) __nv_bfloat16 g_ah[ELEMS];
static __device__ __align__(256) __nv_bfloat16 g_al[ELEMS];
static __device__ __align__(256) __nv_bfloat16 g_wh[4][WELEMS];
static __device__ __align__(256) __nv_bfloat16 g_wl[4][WELEMS];

// ---------------------------------------------------------------------------
__device__ __forceinline__ uint32_t smem_u32(const void* p) {
    uint32_t a;
    asm("{ .reg .u64 t; cvta.to.shared.u64 t, %1; cvt.u32.u64 %0, t; }"
        : "=r"(a) : "l"(p));
    return a;
}
__device__ __forceinline__ void cp16(uint32_t sdst, const void* gsrc) {
    asm volatile("cp.async.cg.shared.global [%0], [%1], 16;" :: "r"(sdst), "l"(gsrc));
}
#define CP_COMMIT() asm volatile("cp.async.commit_group;" ::: "memory")
#define CP_WAIT(n)  asm volatile("cp.async.wait_group %0;" :: "n"(n) : "memory")

__device__ __forceinline__ void ldsm_x4(uint32_t* r, uint32_t addr) {
    asm volatile("ldmatrix.sync.aligned.m8n8.x4.shared.b16 {%0,%1,%2,%3}, [%4];"
                 : "=r"(r[0]), "=r"(r[1]), "=r"(r[2]), "=r"(r[3]) : "r"(addr));
}
__device__ __forceinline__ void mma_bf16(float* c, const uint32_t* a, const uint32_t* b) {
    asm volatile(
        "mma.sync.aligned.m16n8k16.row.col.f32.bf16.bf16.f32 "
        "{%0,%1,%2,%3}, {%4,%5,%6,%7}, {%8,%9}, {%0,%1,%2,%3};"
        : "+f"(c[0]), "+f"(c[1]), "+f"(c[2]), "+f"(c[3])
        : "r"(a[0]), "r"(a[1]), "r"(a[2]), "r"(a[3]), "r"(b[0]), "r"(b[1]));
}

// ---------------------------------------------------------------------------
// GEMM geometry: 64B pitch + XOR swizzle  chunk' = chunk ^ ((row>>1)&3)
//   -> every cp.async store wavefront and every ldmatrix phase (8 consecutive
//      rows, fixed chunk) covers 8 distinct 16B slots mod 128B. Conflict-free.
// ---------------------------------------------------------------------------
#define PITCHB  64               // bytes per row (BK=32 bf16), no padding
#define OPER_B  (128 * PITCHB)   // 8192 bytes per operand per stage
#define STAGE_B (2 * OPER_B)     // 16384 per stage (A then B)
#define NSTAGE  3                // 49152 bytes total = 48KB static limit
#define NKT     96               // virtual K' = 3072, BK = 32
#define TPB     256

__device__ __forceinline__ uint32_t swz(int row, int c) {
    return (uint32_t)(row * PITCHB + ((c ^ ((row >> 1) & 3)) << 4));
}

__device__ __forceinline__ void load_tile(uint32_t sb, int t, int m0, int n0,
                                          const __nv_bfloat16* Ah,
                                          const __nv_bfloat16* Al,
                                          const __nv_bfloat16* Bh,
                                          const __nv_bfloat16* Bl, int tid)
{
    const int pass = t >> 5;                 // 0: Ah*Bh, 1: Ah*Bl, 2: Al*Bh
    const int kb2  = (t & 31) * 64;          // byte offset within a 2048B row
    const char* As = (const char*)((pass == 2) ? Al : Ah) + (size_t)m0 * 2048 + kb2;
    const char* Bs = (const char*)((pass == 1) ? Bl : Bh) + (size_t)n0 * 2048 + kb2;
    const int buf = t - (t / NSTAGE) * NSTAGE;       // t % 3
    const uint32_t dA = sb + buf * STAGE_B;
    const uint32_t dB = dA + OPER_B;
#pragma unroll
    for (int i = 0; i < 2; ++i) {            // 512 chunks per operand / 256 thr
        const int g = tid + i * TPB;
        const int row = g >> 2, c = g & 3;   // 4 x 16B chunks per 64B row
        const uint32_t so = swz(row, c);
        cp16(dA + so, As + (size_t)row * 2048 + c * 16);
        cp16(dB + so, Bs + (size_t)row * 2048 + c * 16);
    }
}

__device__ __forceinline__ void gemm_body(const __nv_bfloat16* Ah,
                                          const __nv_bfloat16* Al,
                                          const __nv_bfloat16* Bh,
                                          const __nv_bfloat16* Bl,
                                          float* __restrict__ C)
{
    __shared__ __align__(16) unsigned char smem[NSTAGE * STAGE_B];  // 48KB
    const uint32_t sb = smem_u32(smem);

    const int tid  = threadIdx.x;
    const int lane = tid & 31, wid = tid >> 5;
    const int wm = wid & 1;                  // 2 warps along M: 64 rows each
    const int wn = wid >> 1;                 // 4 warps along N: 32 cols each
    const int m0 = blockIdx.y * 128, n0 = blockIdx.x * 128;

    // ldmatrix lane geometry (swizzle term invariant under mi*16/n2*16/warp
    // offsets since those are multiples of 8 after >>1).
    const int aRow = wm * 64 + (lane & 15);
    const int sA   = ((lane & 15) >> 1) & 3;
    const int cA0  = lane >> 4;                                   // 0/1
    const int bRow = wn * 32 + (lane & 7) + ((lane >> 4) * 8);
    const int sB   = ((lane & 7) >> 1) & 3;
    const int cB0  = (lane >> 3) & 1;

    float acc[4][4][4];
#pragma unroll
    for (int i = 0; i < 4; ++i)
#pragma unroll
        for (int j = 0; j < 4; ++j)
#pragma unroll
            for (int r = 0; r < 4; ++r) acc[i][j][r] = 0.0f;

    // prologue: tiles 0 and 1 in flight
    load_tile(sb, 0, m0, n0, Ah, Al, Bh, Bl, tid); CP_COMMIT();
    load_tile(sb, 1, m0, n0, Ah, Al, Bh, Bl, tid); CP_COMMIT();

    int buf = 0;   // kt % 3
    for (int kt = 0; kt < NKT; ++kt) {
        // pending groups = {kt, kt+1}; complete tile kt, keep kt+1 flying
        if (kt < NKT - 1) CP_WAIT(1);
        else              CP_WAIT(0);
        __syncthreads();   // tile kt visible; compute kt-1 done by all warps
                           // -> buffer (kt+2)%3 (last read at kt-1) is free

        // refill FIRST: tile kt+2's DMA overlaps compute kt and kt+1
        if (kt + 2 < NKT) {
            load_tile(sb, kt + 2, m0, n0, Ah, Al, Bh, Bl, tid);
            CP_COMMIT();
        }

        const uint32_t stage = sb + buf * STAGE_B;
#pragma unroll
        for (int ks = 0; ks < 2; ++ks) {     // two k16 steps per BK=32
            const uint32_t aCh = (uint32_t)(((cA0 + 2 * ks) ^ sA) << 4);
            const uint32_t bCh = (uint32_t)(((cB0 + 2 * ks) ^ sB) << 4);
            uint32_t a[4][4], b[2][4];
#pragma unroll
            for (int mi = 0; mi < 4; ++mi)
                ldsm_x4(a[mi], stage + (aRow + mi * 16) * PITCHB + aCh);
#pragma unroll
            for (int n2 = 0; n2 < 2; ++n2)   // one x4 feeds two n-tiles
                ldsm_x4(b[n2], stage + OPER_B + (bRow + n2 * 16) * PITCHB + bCh);
#pragma unroll
            for (int mi = 0; mi < 4; ++mi)
#pragma unroll
                for (int ni = 0; ni < 4; ++ni)
                    mma_bf16(acc[mi][ni], a[mi], &b[ni >> 1][(ni & 1) * 2]);
        }
        if (++buf == NSTAGE) buf = 0;
    }

    // epilogue: direct fp32 stores (float2 per half-tile row)
#pragma unroll
    for (int mi = 0; mi < 4; ++mi) {
#pragma unroll
        for (int ni = 0; ni < 4; ++ni) {
            const int m = m0 + wm * 64 + mi * 16 + (lane >> 2);
            const int n = n0 + wn * 32 + ni * 8 + 2 * (lane & 3);
            *(float2*)&C[(size_t)m * DMODEL + n] =
                make_float2(acc[mi][ni][0], acc[mi][ni][1]);
            *(float2*)&C[(size_t)(m + 8) * DMODEL + n] =
                make_float2(acc[mi][ni][2], acc[mi][ni][3]);
        }
    }
}

__global__ __launch_bounds__(TPB, 2)
void k_qkv_mma()
{
    const int z = blockIdx.z;
    float* C = (z == 0) ? g_q : (z == 1) ? g_k : g_v;
    gemm_body(g_xh, g_xl, g_wh[z], g_wl[z], C);
}

__global__ __launch_bounds__(TPB, 2)
void k_out_mma(float* __restrict__ out)
{
    gemm_body(g_ah, g_al, g_wh[3], g_wl[3], out);
}

// ---------------------------------------------------------------------------
// fp32 -> (hi, lo) bf16 split
// ---------------------------------------------------------------------------
__global__ __launch_bounds__(256)
void k_split(const float* __restrict__ src, __nv_bfloat16* __restrict__ dh,
             __nv_bfloat16* __restrict__ dl, int n)
{
    const int i = (blockIdx.x * 256 + threadIdx.x) * 4;
    if (i >= n) return;
    const float4 v = *(const float4*)(src + i);
    __nv_bfloat16 h0 = __float2bfloat16(v.x);
    __nv_bfloat16 h1 = __float2bfloat16(v.y);
    __nv_bfloat16 h2 = __float2bfloat16(v.z);
    __nv_bfloat16 h3 = __float2bfloat16(v.w);
    __nv_bfloat16 l0 = __float2bfloat16(v.x - __bfloat162float(h0));
    __nv_bfloat16 l1 = __float2bfloat16(v.y - __bfloat162float(h1));
    __nv_bfloat16 l2 = __float2bfloat16(v.z - __bfloat162float(h2));
    __nv_bfloat16 l3 = __float2bfloat16(v.w - __bfloat162float(h3));
    *(__nv_bfloat162*)(dh + i)     = __nv_bfloat162(h0, h1);
    *(__nv_bfloat162*)(dh + i + 2) = __nv_bfloat162(h2, h3);
    *(__nv_bfloat162*)(dl + i)     = __nv_bfloat162(l0, l1);
    *(__nv_bfloat162*)(dl + i + 2) = __nv_bfloat162(l2, l3);
}

// ---------------------------------------------------------------------------
// Windowed attention: one warp per (b, h, s); emits bf16 hi/lo split.
// ---------------------------------------------------------------------------
__global__ __launch_bounds__(256)
void k_attn()
{
    const int wg   = (int)((blockIdx.x * blockDim.x + threadIdx.x) >> 5);
    const int lane = threadIdx.x & 31;

    const int s = wg & (S_LEN - 1);
    const int h = (wg >> 12) & (NHEAD - 1);
    const int b = wg >> 16;

    const size_t rowbase = ((size_t)(b * S_LEN + s)) * DMODEL + h * HDIM;
    const float2 qv = *(const float2*)(g_q + rowbase + 2 * lane);

    float sc[WIN];
#pragma unroll
    for (int j = 0; j < WIN; ++j) {
        const int sp = s + j - LPAD;
        float val = -1e30f;
        if (sp >= 0 && sp < S_LEN) {
            const size_t kb = ((size_t)(b * S_LEN + sp)) * DMODEL + h * HDIM;
            const float2 kv = *(const float2*)(g_k + kb + 2 * lane);
            float p = qv.x * kv.x + qv.y * kv.y;
            p += __shfl_xor_sync(0xffffffffu, p, 16);
            p += __shfl_xor_sync(0xffffffffu, p, 8);
            p += __shfl_xor_sync(0xffffffffu, p, 4);
            p += __shfl_xor_sync(0xffffffffu, p, 2);
            p += __shfl_xor_sync(0xffffffffu, p, 1);
            val = p * 0.125f;   // 1/sqrt(64)
        }
        sc[j] = val;
    }

    float mx = sc[0];
#pragma unroll
    for (int j = 1; j < WIN; ++j) mx = fmaxf(mx, sc[j]);

    float den = 0.0f, ax = 0.0f, ay = 0.0f;
#pragma unroll
    for (int j = 0; j < WIN; ++j) {
        const int sp = s + j - LPAD;
        if (sp >= 0 && sp < S_LEN) {
            const float p = __expf(sc[j] - mx);
            den += p;
            const size_t vb = ((size_t)(b * S_LEN + sp)) * DMODEL + h * HDIM;
            const float2 vv = *(const float2*)(g_v + vb + 2 * lane);
            ax = fmaf(p, vv.x, ax);
            ay = fmaf(p, vv.y, ay);
        }
    }
    const float inv = 1.0f / den;
    const float ox = ax * inv, oy = ay * inv;
    const __nv_bfloat16 hx = __float2bfloat16(ox);
    const __nv_bfloat16 hy = __float2bfloat16(oy);
    const __nv_bfloat16 lx = __float2bfloat16(ox - __bfloat162float(hx));
    const __nv_bfloat16 ly = __float2bfloat16(oy - __bfloat162float(hy));
    *(__nv_bfloat162*)(g_ah + rowbase + 2 * lane) = __nv_bfloat162(hx, hy);
    *(__nv_bfloat162*)(g_al + rowbase + 2 * lane) = __nv_bfloat162(lx, ly);
}

// ---------------------------------------------------------------------------
extern "C" void kernel_launch(void* const* d_in, const int* in_sizes, int n_in,
                              void* d_out, int out_size)
{
    (void)in_sizes; (void)n_in; (void)out_size;
    const float* x  = (const float*)d_in[0];
    const float* Wq = (const float*)d_in[1];
    const float* Wk = (const float*)d_in[2];
    const float* Wv = (const float*)d_in[3];
    const float* Wo = (const float*)d_in[4];
    float* out = (float*)d_out;

    // NOTE: no cudaFuncSetAttribute anywhere — smem is static and <= 48KB.
    __nv_bfloat16 *xh, *xl, *wh, *wl;
    cudaGetSymbolAddress((void**)&xh, g_xh);
    cudaGetSymbolAddress((void**)&xl, g_xl);
    cudaGetSymbolAddress((void**)&wh, g_wh);
    cudaGetSymbolAddress((void**)&wl, g_wl);

    k_split<<<ELEMS / 1024, 256>>>(x,  xh, xl, ELEMS);
    k_split<<<WELEMS / 1024, 256>>>(Wq, wh + 0 * (size_t)WELEMS, wl + 0 * (size_t)WELEMS, WELEMS);
    k_split<<<WELEMS / 1024, 256>>>(Wk, wh + 1 * (size_t)WELEMS, wl + 1 * (size_t)WELEMS, WELEMS);
    k_split<<<WELEMS / 1024, 256>>>(Wv, wh + 2 * (size_t)WELEMS, wl + 2 * (size_t)WELEMS, WELEMS);
    k_split<<<WELEMS / 1024, 256>>>(Wo, wh + 3 * (size_t)WELEMS, wl + 3 * (size_t)WELEMS, WELEMS);

    k_qkv_mma<<<dim3(8, 64, 3), TPB>>>();

    const int total_warps = BATCH * NHEAD * S_LEN;          // 131072
    k_attn<<<total_warps / 8, 256>>>();

    k_out_mma<<<dim3(8, 64), TPB>>>(out);
}